// round 7
// baseline (speedup 1.0000x reference)
#include <cuda_runtime.h>
#include <cuda_fp16.h>
#include <cstdint>

// ======================= constants ==========================================
namespace {
constexpr int SA_BYTES    = 256 * 128;                 // A: 256 rows x 128B = 32 KB
constexpr int SB_BYTES    = 128 * 128;                 // B: 128 rows x 128B = 16 KB
constexpr int STAGE_BYTES = SA_BYTES + SB_BYTES;       // 48 KB
constexpr int OFF_BETA    = 2 * STAGE_BYTES;           // after both stages
constexpr int SMEM_DYN    = 2 * STAGE_BYTES + 768;     // + beta + slack
}

__constant__ float c_sign[64] = {
    +1,-1,-1,-1,-1,-1,-1,-1,  +1,+1,+1,-1,+1,-1,-1,+1,
    +1,-1,+1,+1,+1,+1,-1,-1,  +1,+1,-1,+1,+1,-1,+1,-1,
    +1,-1,-1,-1,+1,+1,+1,+1,  +1,+1,-1,+1,-1,+1,-1,+1,
    +1,+1,+1,-1,-1,+1,+1,-1,  +1,-1,+1,+1,-1,-1,+1,+1};

// x converted to fp16 (same layout as x): [8][8][4096][128]
__device__ __align__(16) __half g_xh[8 * 8 * 4096 * 128];
// signed, transposed, SW128-preswizzled weights: [i(8)][j(8)][h(2)] x (128e x 64d) fp16
__device__ __align__(16) __half g_Wh[8 * 8 * 2 * 128 * 64];

// ======================= helpers ============================================
__device__ __forceinline__ uint32_t smem_u32(const void* p) {
    uint32_t a;
    asm("{ .reg .u64 t; cvta.to.shared.u64 t, %1; cvt.u32.u64 %0, t; }" : "=r"(a) : "l"(p));
    return a;
}
#define SW128(o) ((o) ^ (((o) >> 3) & 0x70))
#define CP_ASYNC16(dst, src) \
    asm volatile("cp.async.cg.shared.global [%0], [%1], 16;" :: "r"(dst), "l"(src) : "memory")
#define CP_COMMIT() asm volatile("cp.async.commit_group;" ::: "memory")
#define CP_WAIT0()  asm volatile("cp.async.wait_group 0;" ::: "memory")
#define CP_WAIT1()  asm volatile("cp.async.wait_group 1;" ::: "memory")
#define LDMATRIX_X4(r0, r1, r2, r3, addr) \
    asm volatile("ldmatrix.sync.aligned.m8n8.x4.shared.b16 {%0,%1,%2,%3}, [%4];" \
        : "=r"(r0), "=r"(r1), "=r"(r2), "=r"(r3) : "r"(addr))
#define MMA16816(c, a, b0, b1) \
    asm volatile("mma.sync.aligned.m16n8k16.row.col.f32.f16.f16.f32 " \
        "{%0,%1,%2,%3}, {%4,%5,%6,%7}, {%8,%9}, {%0,%1,%2,%3};" \
        : "+f"((c)[0]), "+f"((c)[1]), "+f"((c)[2]), "+f"((c)[3]) \
        : "r"((a)[0]), "r"((a)[1]), "r"((a)[2]), "r"((a)[3]), "r"(b0), "r"(b1))

// ======================= prep: x -> fp16 ====================================
__global__ void octo_prep_x(const float* __restrict__ x) {
    const size_t gid = (size_t)blockIdx.x * blockDim.x + threadIdx.x;  // 4,194,304
    const size_t base = gid * 8;
    const float4 f0 = reinterpret_cast<const float4*>(x + base)[0];
    const float4 f1 = reinterpret_cast<const float4*>(x + base)[1];
    uint32_t w0, w1, w2, w3;
    asm("cvt.rn.f16x2.f32 %0, %1, %2;" : "=r"(w0) : "f"(f0.y), "f"(f0.x));
    asm("cvt.rn.f16x2.f32 %0, %1, %2;" : "=r"(w1) : "f"(f0.w), "f"(f0.z));
    asm("cvt.rn.f16x2.f32 %0, %1, %2;" : "=r"(w2) : "f"(f1.y), "f"(f1.x));
    asm("cvt.rn.f16x2.f32 %0, %1, %2;" : "=r"(w3) : "f"(f1.w), "f"(f1.z));
    reinterpret_cast<uint4*>(g_xh + base)[0] = make_uint4(w0, w1, w2, w3);
}

// ======================= prep: weights ======================================
// tile(i,j,h): [e=0..127 rows of 128B][d0=0..63], SW128-swizzled,
// element = sign[i][j] * W[i^j][h*64+d0][e]
__global__ void octo_prep_w(const float* __restrict__ W) {
    const int blk = blockIdx.x;              // 128 = i*16 + j*2 + h
    const int i = blk >> 4, j = (blk >> 1) & 7, h = blk & 1;
    const int k = i ^ j;
    const float s = c_sign[i * 8 + j];
    const size_t tile = (size_t)((i * 8 + j) * 2 + h) * 16384;  // bytes
    for (int u = threadIdx.x; u < 1024; u += blockDim.x) {
        const int e = u >> 3, seg = u & 7;   // seg: 8 d-halves per 16B unit
        const float* src = W + ((size_t)k * 128 + h * 64 + seg * 8) * 128 + e;
        uint32_t wd[4];
#pragma unroll
        for (int m = 0; m < 4; m++) {
            float lo = s * src[(2 * m) * 128];
            float hi = s * src[(2 * m + 1) * 128];
            asm("cvt.rn.f16x2.f32 %0, %1, %2;" : "=r"(wd[m]) : "f"(hi), "f"(lo));
        }
        const uint32_t off = SW128((uint32_t)(e * 128 + seg * 16));
        *reinterpret_cast<uint4*>(reinterpret_cast<char*>(g_Wh) + tile + off) =
            make_uint4(wd[0], wd[1], wd[2], wd[3]);
    }
}

// ======================= main GEMM ==========================================
// grid: (i=8, mtile=128); CTA: 512 threads; M=256, N=128, K=1024 (16 stages of 64)
__global__ void __launch_bounds__(512, 1)
octo_gemm(const float* __restrict__ beta, float* __restrict__ out) {
    extern __shared__ char smem_raw[];
    const uint32_t sb = smem_u32(smem_raw);
    const int tid = threadIdx.x;
    const int lane = tid & 31;
    const int w = tid >> 5;                   // 16 warps
    const int wm = w & 7, wn = w >> 3;        // 8 x 2 warp grid
    const int m0 = wm * 32, n0 = wn * 64;

    const int i = blockIdx.x;                 // head (fastest -> A shared in L2)
    const int mt = blockIdx.y;                // 128 m-tiles
    const int b = mt >> 4;
    const int tc = (mt & 15) * 256;

    if (tid < 128)
        asm volatile("st.shared.f32 [%0], %1;"
                     :: "r"(sb + OFF_BETA + tid * 4), "f"(beta[tid]) : "memory");

    auto load_stage = [&](int buf, int step) {
        const int j = step >> 1, h = step & 1;
        const uint32_t sA = sb + buf * STAGE_BYTES;
        const uint32_t sB = sA + SA_BYTES;
        const __half* asrc = g_xh + ((size_t)(b * 8 + j) * 4096 + tc) * 128 + h * 64;
#pragma unroll
        for (int q = 0; q < 4; ++q) {
            const int unit = q * 512 + tid;   // 2048 units: row(256) x seg(8)
            const int row = unit >> 3, seg = unit & 7;
            CP_ASYNC16(sA + SW128((uint32_t)(row * 128 + seg * 16)),
                       asrc + (size_t)row * 128 + seg * 8);
        }
        const char* bsrc = reinterpret_cast<const char*>(g_Wh) +
                           (size_t)((i * 8 + j) * 2 + h) * 16384;
#pragma unroll
        for (int q = 0; q < 2; ++q) {
            const int unit = q * 512 + tid;   // 1024 linear 16B units (pre-swizzled)
            CP_ASYNC16(sB + unit * 16, bsrc + (size_t)unit * 16);
        }
    };

    float acc[2][8][4];
#pragma unroll
    for (int a = 0; a < 2; ++a)
#pragma unroll
        for (int c = 0; c < 8; ++c)
#pragma unroll
            for (int q = 0; q < 4; ++q) acc[a][c][q] = 0.f;

    const uint32_t aRowOff = (uint32_t)((m0 + (lane & 15)) * 128 + (lane >> 4) * 16);
    const uint32_t bRowOff = (uint32_t)((n0 + (lane & 15)) * 128 + (lane >> 4) * 16);

    load_stage(0, 0);
    CP_COMMIT();

    for (int step = 0; step < 16; ++step) {
        const int s = step & 1;
        if (step < 15) { load_stage(s ^ 1, step + 1); CP_COMMIT(); CP_WAIT1(); }
        else           { CP_WAIT0(); }
        __syncthreads();

        const uint32_t sA = sb + s * STAGE_BYTES;
        const uint32_t sB = sA + SA_BYTES;
#pragma unroll
        for (int ks = 0; ks < 4; ++ks) {
            const uint32_t col = ks * 32;
            uint32_t a[2][4];
#pragma unroll
            for (int mf = 0; mf < 2; ++mf) {
                uint32_t off = aRowOff + mf * 2048 + col;
                LDMATRIX_X4(a[mf][0], a[mf][1], a[mf][2], a[mf][3], sA + SW128(off));
            }
#pragma unroll
            for (int nt = 0; nt < 4; ++nt) {
                uint32_t off = bRowOff + nt * 2048 + col;
                uint32_t b0, b1, b2, b3;
                LDMATRIX_X4(b0, b1, b2, b3, sB + SW128(off));
                // b-frags: n8 lo = {b0,b2}, n8 hi = {b1,b3}
#pragma unroll
                for (int mf = 0; mf < 2; ++mf) {
                    MMA16816(acc[mf][nt * 2 + 0], a[mf], b0, b2);
                    MMA16816(acc[mf][nt * 2 + 1], a[mf], b1, b3);
                }
            }
        }
        __syncthreads();
    }

    // ---- epilogue: beta scale + store ----
    const int g = lane >> 2, cl = lane & 3;
    float* obase = out + ((size_t)(b * 8 + i) * 4096 + tc) * 128;
#pragma unroll
    for (int mf = 0; mf < 2; ++mf) {
#pragma unroll
        for (int nf = 0; nf < 8; ++nf) {
            const int e = n0 + nf * 8 + cl * 2;
            float2 b2;
            asm volatile("ld.shared.v2.f32 {%0,%1}, [%2];"
                         : "=f"(b2.x), "=f"(b2.y) : "r"(sb + OFF_BETA + e * 4));
            const int row = m0 + mf * 16 + g;
            float2 v0 = make_float2(acc[mf][nf][0] * b2.x, acc[mf][nf][1] * b2.y);
            float2 v1 = make_float2(acc[mf][nf][2] * b2.x, acc[mf][nf][3] * b2.y);
            *reinterpret_cast<float2*>(obase + (size_t)row * 128 + e) = v0;
            *reinterpret_cast<float2*>(obase + (size_t)(row + 8) * 128 + e) = v1;
        }
    }
}

// ======================= launch =============================================
extern "C" void kernel_launch(void* const* d_in, const int* in_sizes, int n_in,
                              void* d_out, int out_size) {
    const float* x    = (const float*)d_in[0];
    const float* W    = (const float*)d_in[1];
    const float* beta = (const float*)d_in[2];
    float* out = (float*)d_out;
    (void)in_sizes; (void)n_in; (void)out_size;

    cudaFuncSetAttribute(octo_gemm, cudaFuncAttributeMaxDynamicSharedMemorySize, SMEM_DYN);
    octo_prep_x<<<16384, 256>>>(x);
    octo_prep_w<<<128, 256>>>(W);
    octo_gemm<<<dim3(8, 128), 512, SMEM_DYN>>>(beta, out);
}